// round 5
// baseline (speedup 1.0000x reference)
#include <cuda_runtime.h>
#include <cuda_bf16.h>

#define N_NODES 100000
#define N_EDGES 1000000
#define DIM 64
#define EDIM 16
#define SCAN_BS 512
#define SCAN_NBLK ((N_NODES + SCAN_BS - 1) / SCAN_BS)   // 196

__device__ int g_idx_is64;

// CSR scratch (static device globals -- no allocation)
__device__ int    g_cnt[N_NODES];
__device__ int    g_off[N_NODES];
__device__ int    g_cur[N_NODES];
__device__ int    g_bsum[SCAN_NBLK];
__device__ int    g_bbase[SCAN_NBLK];
__device__ int    g_src[N_EDGES];          // dst-sorted src ids (4 MB)
__device__ float4 g_eas[N_EDGES * 4];      // dst-sorted edge_attr rows (64 MB)

// ---------------------------------------------------------------------------
// packed fp32x2 helpers
// ---------------------------------------------------------------------------
__device__ __forceinline__ unsigned long long f2_as_u64(float a, float b) {
    unsigned long long r;
    asm("mov.b64 %0, {%1, %2};" : "=l"(r) : "f"(a), "f"(b));
    return r;
}
__device__ __forceinline__ void u64_as_f2(unsigned long long v, float& a, float& b) {
    asm("mov.b64 {%0, %1}, %2;" : "=f"(a), "=f"(b) : "l"(v));
}
__device__ __forceinline__ void ffma2(unsigned long long& d,
                                      unsigned long long a, unsigned long long b) {
    asm("fma.rn.f32x2 %0, %1, %2, %0;" : "+l"(d) : "l"(a), "l"(b));
}

// ---------------------------------------------------------------------------
// init: zero histogram everywhere; block 0 also detects index dtype
// ---------------------------------------------------------------------------
__global__ void init_kernel(const unsigned int* __restrict__ w) {
    int i = blockIdx.x * 256 + threadIdx.x;
    if (i < N_NODES) g_cnt[i] = 0;
    if (blockIdx.x == 0) {
        __shared__ unsigned int nz[8];
        unsigned int v = w[2 * threadIdx.x + 1];
        unsigned int any = __ballot_sync(0xffffffffu, v != 0u);
        if ((threadIdx.x & 31) == 0) nz[threadIdx.x >> 5] = any;
        __syncthreads();
        if (threadIdx.x == 0) {
            unsigned int a = 0;
#pragma unroll
            for (int k = 0; k < 8; k++) a |= nz[k];
            g_idx_is64 = (a == 0u) ? 1 : 0;
        }
    }
}

// ---------------------------------------------------------------------------
// histogram of dst
// ---------------------------------------------------------------------------
__global__ void hist_kernel(const void* __restrict__ ei_raw) {
    int e = blockIdx.x * 256 + threadIdx.x;
    if (e >= N_EDGES) return;
    int dst = g_idx_is64 ? (int)((const long long*)ei_raw)[N_EDGES + e]
                         : ((const int*)ei_raw)[N_EDGES + e];
    atomicAdd(&g_cnt[dst], 1);
}

// ---------------------------------------------------------------------------
// exclusive scan of g_cnt -> g_off, g_cur   (3 kernels, all parallel)
// ---------------------------------------------------------------------------
__global__ void scan1_kernel() {
    __shared__ int sh[SCAN_BS];
    int idx = blockIdx.x * SCAN_BS + threadIdx.x;
    sh[threadIdx.x] = (idx < N_NODES) ? g_cnt[idx] : 0;
    __syncthreads();
    for (int o = SCAN_BS / 2; o > 0; o >>= 1) {
        if (threadIdx.x < o) sh[threadIdx.x] += sh[threadIdx.x + o];
        __syncthreads();
    }
    if (threadIdx.x == 0) g_bsum[blockIdx.x] = sh[0];
}

__global__ void scan2_kernel() {          // parallel scan of 196 partials
    __shared__ int sh[256];
    int t = threadIdx.x;
    int v = (t < SCAN_NBLK) ? g_bsum[t] : 0;
    sh[t] = v;
    __syncthreads();
    for (int o = 1; o < 256; o <<= 1) {
        int tmp = (t >= o) ? sh[t - o] : 0;
        __syncthreads();
        sh[t] += tmp;
        __syncthreads();
    }
    if (t < SCAN_NBLK) g_bbase[t] = sh[t] - v;   // exclusive
}

__global__ void scan3_kernel() {
    __shared__ int sh[SCAN_BS];
    int idx = blockIdx.x * SCAN_BS + threadIdx.x;
    int v = (idx < N_NODES) ? g_cnt[idx] : 0;
    sh[threadIdx.x] = v;
    __syncthreads();
    for (int o = 1; o < SCAN_BS; o <<= 1) {
        int t = (threadIdx.x >= o) ? sh[threadIdx.x - o] : 0;
        __syncthreads();
        sh[threadIdx.x] += t;
        __syncthreads();
    }
    if (idx < N_NODES) {
        int ex = g_bbase[blockIdx.x] + sh[threadIdx.x] - v;
        g_off[idx] = ex;
        g_cur[idx] = ex;
    }
}

// ---------------------------------------------------------------------------
// build: scatter src + FULL edge_attr row into dst-sorted order.
// Aggregate then reads ea with zero indirection.
// ---------------------------------------------------------------------------
__global__ void build_kernel(const void* __restrict__ ei_raw,
                             const float4* __restrict__ ea4) {
    int e = blockIdx.x * 256 + threadIdx.x;
    if (e >= N_EDGES) return;
    int src, dst;
    if (g_idx_is64) {
        const long long* ei = (const long long*)ei_raw;
        src = (int)ei[e];
        dst = (int)ei[N_EDGES + e];
    } else {
        const int* ei = (const int*)ei_raw;
        src = ei[e];
        dst = ei[N_EDGES + e];
    }
    int pos = atomicAdd(&g_cur[dst], 1);
    g_src[pos] = src;
    float4 a0 = __ldcs(&ea4[e * 4 + 0]);
    float4 a1 = __ldcs(&ea4[e * 4 + 1]);
    float4 a2 = __ldcs(&ea4[e * 4 + 2]);
    float4 a3 = __ldcs(&ea4[e * 4 + 3]);
    g_eas[pos * 4 + 0] = a0;
    g_eas[pos * 4 + 1] = a1;
    g_eas[pos * 4 + 2] = a2;
    g_eas[pos * 4 + 3] = a3;
}

// ---------------------------------------------------------------------------
// aggregate: per-node gather-sum, no float atomics, software-pipelined.
// 2 nodes/warp, 16 lanes/node, lane owns 4 cols.
//   out[n] = sum_j relu(x[src_j] + ea_j @ We + be)
// ea rows: sequential addresses (no indirection). src prefetched distance 2,
// payload (ea row + x row) prefetched distance 1.
// ---------------------------------------------------------------------------
__global__ __launch_bounds__(256) void aggregate_kernel(
    const float4* __restrict__ x4,
    const float4* __restrict__ We4,
    const float4* __restrict__ be4,
    float4* __restrict__ out4)
{
    __shared__ float4 Wes[EDIM * 16];   // We row-major verbatim, 4 KB

    int tid = threadIdx.x;
    for (int i = tid; i < EDIM * 16; i += 256) Wes[i] = We4[i];
    __syncthreads();

    int w    = blockIdx.x * 8 + (tid >> 5);
    int lane = tid & 31;
    int l    = lane & 15;
    int n    = w * 2 + (lane >> 4);                // exact grid

    int off = g_off[n], deg = g_cnt[n];

    ulonglong2 be2 = ((const ulonglong2*)be4)[l];
    float4 acc = make_float4(0.f, 0.f, 0.f, 0.f);

    // pipeline state
    float4 A0, A1, A2, A3, xv;
    int s_next;
    if (deg > 0) {
        const float4* r = &g_eas[(size_t)off * 4];
        A0 = __ldcs(r + 0); A1 = __ldcs(r + 1);
        A2 = __ldcs(r + 2); A3 = __ldcs(r + 3);
        int s0 = __ldcs(&g_src[off]);
        xv = x4[(size_t)s0 * 16 + l];
        s_next = (deg > 1) ? __ldcs(&g_src[off + 1]) : 0;
    }

    for (int j = 0; j < deg; j++) {
        float4 B0 = A0, B1 = A1, B2 = A2, B3 = A3, xb = xv;
        if (j + 1 < deg) {
            const float4* r = &g_eas[(size_t)(off + j + 1) * 4];
            A0 = __ldcs(r + 0); A1 = __ldcs(r + 1);
            A2 = __ldcs(r + 2); A3 = __ldcs(r + 3);
            xv = x4[(size_t)s_next * 16 + l];
            if (j + 2 < deg) s_next = __ldcs(&g_src[off + j + 2]);
        }

        unsigned long long p0 = be2.x, p1 = be2.y;
#define STEP(k, a) { unsigned long long av = f2_as_u64((a), (a));              \
                     ulonglong2 wv = *(const ulonglong2*)&Wes[(k) * 16 + l];   \
                     ffma2(p0, av, wv.x); ffma2(p1, av, wv.y); }
        STEP(0,  B0.x) STEP(1,  B0.y) STEP(2,  B0.z) STEP(3,  B0.w)
        STEP(4,  B1.x) STEP(5,  B1.y) STEP(6,  B1.z) STEP(7,  B1.w)
        STEP(8,  B2.x) STEP(9,  B2.y) STEP(10, B2.z) STEP(11, B2.w)
        STEP(12, B3.x) STEP(13, B3.y) STEP(14, B3.z) STEP(15, B3.w)
#undef STEP
        float m0, m1, m2, m3;
        u64_as_f2(p0, m0, m1);
        u64_as_f2(p1, m2, m3);
        acc.x += fmaxf(m0 + xb.x, 0.f);
        acc.y += fmaxf(m1 + xb.y, 0.f);
        acc.z += fmaxf(m2 + xb.z, 0.f);
        acc.w += fmaxf(m3 + xb.w, 0.f);
    }
    out4[(size_t)n * 16 + l] = acc;
}

// ---------------------------------------------------------------------------
// Node epilogue: 8 nodes/warp, packed f32x2 MLP + LayerNorm + ReLU
// ---------------------------------------------------------------------------
#define NPW 8
__global__ __launch_bounds__(256, 4) void node_kernel(
    const float2* __restrict__ x,
    const float* __restrict__ W1,
    const float* __restrict__ b1,
    const float* __restrict__ W2,
    const float* __restrict__ b2,
    const float* __restrict__ gamma,
    const float* __restrict__ beta,
    float2* __restrict__ out)     // holds aggr on entry; overwritten in place
{
    __shared__ unsigned long long W1p[32 * 64];   // 16 KB
    __shared__ unsigned long long W2p[32 * 64];   // 16 KB
    __shared__ float hs[8][NPW * DIM];            // 16 KB

    int tid = threadIdx.x;
    for (int i = tid; i < 32 * 64; i += 256) {
        int k2 = i >> 6, c = i & 63;
        W1p[i] = f2_as_u64(W1[(2 * k2) * 64 + c], W1[(2 * k2 + 1) * 64 + c]);
        W2p[i] = f2_as_u64(W2[(2 * k2) * 64 + c], W2[(2 * k2 + 1) * 64 + c]);
    }
    __syncthreads();

    int w = tid >> 5, lane = tid & 31;
    int base = (blockIdx.x * 8 + w) * NPW;
    if (base >= N_NODES) return;
    float* h = hs[w];

#pragma unroll
    for (int n = 0; n < NPW; n++) {
        int node = base + n;
        if (node < N_NODES) {
            float2 xv = x[(size_t)node * 32 + lane];
            float2 av = out[(size_t)node * 32 + lane];
            *(float2*)&h[n * DIM + 2 * lane] = make_float2(xv.x + av.x, xv.y + av.y);
        }
    }
    __syncwarp();

    unsigned long long accA[NPW], accB[NPW];

    // ---- layer 1 ----
    {
        float bA = b1[2 * lane], bB = b1[2 * lane + 1];
#pragma unroll
        for (int n = 0; n < NPW; n++) {
            accA[n] = f2_as_u64(bA, 0.f);
            accB[n] = f2_as_u64(bB, 0.f);
        }
    }
#pragma unroll
    for (int k2 = 0; k2 < 32; k2++) {
        ulonglong2 wp = *(const ulonglong2*)&W1p[k2 * 64 + 2 * lane];
#pragma unroll
        for (int n = 0; n < NPW; n++) {
            unsigned long long h2 = *(const unsigned long long*)&h[n * DIM + 2 * k2];
            ffma2(accA[n], h2, wp.x);
            ffma2(accB[n], h2, wp.y);
        }
    }
    __syncwarp();
#pragma unroll
    for (int n = 0; n < NPW; n++) {
        float ax, ay, bx, by;
        u64_as_f2(accA[n], ax, ay);
        u64_as_f2(accB[n], bx, by);
        *(float2*)&h[n * DIM + 2 * lane] =
            make_float2(fmaxf(ax + ay, 0.f), fmaxf(bx + by, 0.f));
    }
    __syncwarp();

    // ---- layer 2 ----
    {
        float bA = b2[2 * lane], bB = b2[2 * lane + 1];
#pragma unroll
        for (int n = 0; n < NPW; n++) {
            accA[n] = f2_as_u64(bA, 0.f);
            accB[n] = f2_as_u64(bB, 0.f);
        }
    }
#pragma unroll
    for (int k2 = 0; k2 < 32; k2++) {
        ulonglong2 wp = *(const ulonglong2*)&W2p[k2 * 64 + 2 * lane];
#pragma unroll
        for (int n = 0; n < NPW; n++) {
            unsigned long long h2 = *(const unsigned long long*)&h[n * DIM + 2 * k2];
            ffma2(accA[n], h2, wp.x);
            ffma2(accB[n], h2, wp.y);
        }
    }

    // ---- LayerNorm + ReLU ----
    float2 g  = make_float2(gamma[2 * lane], gamma[2 * lane + 1]);
    float2 bt = make_float2(beta[2 * lane],  beta[2 * lane + 1]);
    const float inv = 1.0f / DIM;

#pragma unroll
    for (int n = 0; n < NPW; n++) {
        float ax, ay, bx, by;
        u64_as_f2(accA[n], ax, ay);
        u64_as_f2(accB[n], bx, by);
        float v0 = ax + ay, v1 = bx + by;
        float s = v0 + v1, q = v0 * v0 + v1 * v1;
#pragma unroll
        for (int o = 16; o > 0; o >>= 1) {
            s += __shfl_xor_sync(0xffffffffu, s, o);
            q += __shfl_xor_sync(0xffffffffu, q, o);
        }
        float mu  = s * inv;
        float var = fmaxf(q * inv - mu * mu, 0.f);
        float r   = rsqrtf(var + 1e-5f);
        int node = base + n;
        if (node < N_NODES) {
            float2 o2;
            o2.x = fmaxf((v0 - mu) * r * g.x + bt.x, 0.f);
            o2.y = fmaxf((v1 - mu) * r * g.y + bt.y, 0.f);
            out[(size_t)node * 32 + lane] = o2;
        }
    }
}

// ---------------------------------------------------------------------------
// Launch
// ---------------------------------------------------------------------------
extern "C" void kernel_launch(void* const* d_in, const int* in_sizes, int n_in,
                              void* d_out, int out_size) {
    const float* x     = (const float*)d_in[0];
    const void*  ei    = d_in[1];
    const float* ea    = (const float*)d_in[2];
    const float* We    = (const float*)d_in[3];
    const float* be    = (const float*)d_in[4];
    const float* W1    = (const float*)d_in[5];
    const float* b1    = (const float*)d_in[6];
    const float* W2    = (const float*)d_in[7];
    const float* b2    = (const float*)d_in[8];
    const float* gamma = (const float*)d_in[9];
    const float* beta  = (const float*)d_in[10];
    float* out = (float*)d_out;

    init_kernel<<<(N_NODES + 255) / 256, 256>>>((const unsigned int*)ei);
    hist_kernel<<<(N_EDGES + 255) / 256, 256>>>(ei);
    scan1_kernel<<<SCAN_NBLK, SCAN_BS>>>();
    scan2_kernel<<<1, 256>>>();
    scan3_kernel<<<SCAN_NBLK, SCAN_BS>>>();
    build_kernel<<<(N_EDGES + 255) / 256, 256>>>(ei, (const float4*)ea);

    aggregate_kernel<<<N_NODES / 16, 256>>>((const float4*)x,
                                            (const float4*)We, (const float4*)be,
                                            (float4*)out);

    node_kernel<<<(N_NODES + 63) / 64, 256>>>((const float2*)x, W1, b1, W2, b2,
                                              gamma, beta, (float2*)out);
}

// round 6
// speedup vs baseline: 1.1410x; 1.1410x over previous
#include <cuda_runtime.h>
#include <cuda_bf16.h>

#define N_NODES 100000
#define N_EDGES 1000000
#define DIM 64
#define EDIM 16

// Flag: 1 if edge_index is int64, 0 if int32.
__device__ int g_idx_is64;

// ---------------------------------------------------------------------------
// packed fp32x2 helpers (Blackwell FFMA2)
// ---------------------------------------------------------------------------
__device__ __forceinline__ unsigned long long f2_as_u64(float a, float b) {
    unsigned long long r;
    asm("mov.b64 %0, {%1, %2};" : "=l"(r) : "f"(a), "f"(b));
    return r;
}
__device__ __forceinline__ void u64_as_f2(unsigned long long v, float& a, float& b) {
    asm("mov.b64 {%0, %1}, %2;" : "=f"(a), "=f"(b) : "l"(v));
}
__device__ __forceinline__ void ffma2(unsigned long long& d,
                                      unsigned long long a, unsigned long long b) {
    asm("fma.rn.f32x2 %0, %1, %2, %0;" : "+l"(d) : "l"(a), "l"(b));
}

// ---------------------------------------------------------------------------
// Kernel 1: zero accumulator (d_out) + detect index dtype (block 0)
// ---------------------------------------------------------------------------
__global__ void zero_detect_kernel(float4* __restrict__ out, int n4,
                                   const unsigned int* __restrict__ w) {
    int i = blockIdx.x * 256 + threadIdx.x;
    if (i < n4) out[i] = make_float4(0.f, 0.f, 0.f, 0.f);
    if (blockIdx.x == 0) {
        __shared__ unsigned int nz[8];
        unsigned int v = w[2 * threadIdx.x + 1];
        unsigned int any = __ballot_sync(0xffffffffu, v != 0u);
        if ((threadIdx.x & 31) == 0) nz[threadIdx.x >> 5] = any;
        __syncthreads();
        if (threadIdx.x == 0) {
            unsigned int a = 0;
#pragma unroll
            for (int k = 0; k < 8; k++) a |= nz[k];
            g_idx_is64 = (a == 0u) ? 1 : 0;
        }
    }
}

// ---------------------------------------------------------------------------
// Kernel 2: per-edge message + scatter.  2 edges/warp, 16 lanes/edge, lane
// owns 4 cols as two packed f32x2 accumulators; red.global.add.v4.f32.
//   msg = relu(x[src] + ea @ We + be);  aggr[dst] += msg
// ea row read as 4 broadcast LDG.128 (no shuffle chain).
// ---------------------------------------------------------------------------
__global__ __launch_bounds__(256) void edge_kernel(
    const float4* __restrict__ x4,
    const void* __restrict__ ei_raw,
    const float4* __restrict__ ea4,
    const float4* __restrict__ be4,
    const float4* __restrict__ We4,
    float* __restrict__ aggr)
{
    __shared__ float4 Wes[EDIM * 16];   // We row-major verbatim, 4 KB

    int tid = threadIdx.x;
    for (int i = tid; i < EDIM * 16; i += 256) Wes[i] = We4[i];
    __syncthreads();

    int gw   = blockIdx.x * 8 + (tid >> 5);
    int lane = tid & 31;
    int half = lane >> 4, l = lane & 15;
    int e = gw * 2 + half;              // exact grid, no tail

    int src, dst;
    if (g_idx_is64) {
        const long long* ei = (const long long*)ei_raw;
        src = (int)__ldcs(&ei[e]);
        dst = (int)__ldcs(&ei[N_EDGES + e]);
    } else {
        const int* ei = (const int*)ei_raw;
        src = __ldcs(&ei[e]);
        dst = __ldcs(&ei[N_EDGES + e]);
    }

    // full ea row, broadcast across the 16 lanes of this half (streaming)
    const float4* ear = ea4 + (size_t)e * 4;
    float4 A0 = __ldcs(ear + 0);
    float4 A1 = __ldcs(ear + 1);
    float4 A2 = __ldcs(ear + 2);
    float4 A3 = __ldcs(ear + 3);

    ulonglong2 be2 = ((const ulonglong2*)be4)[l];
    unsigned long long p0 = be2.x, p1 = be2.y;

#define STEP(k, a) { unsigned long long av = f2_as_u64((a), (a));              \
                     ulonglong2 wv = *(const ulonglong2*)&Wes[(k) * 16 + l];   \
                     ffma2(p0, av, wv.x); ffma2(p1, av, wv.y); }
    STEP(0,  A0.x) STEP(1,  A0.y) STEP(2,  A0.z) STEP(3,  A0.w)
    STEP(4,  A1.x) STEP(5,  A1.y) STEP(6,  A1.z) STEP(7,  A1.w)
    STEP(8,  A2.x) STEP(9,  A2.y) STEP(10, A2.z) STEP(11, A2.w)
    STEP(12, A3.x) STEP(13, A3.y) STEP(14, A3.z) STEP(15, A3.w)
#undef STEP

    float4 xv = x4[(size_t)src * 16 + l];
    float m0, m1, m2, m3;
    u64_as_f2(p0, m0, m1);
    u64_as_f2(p1, m2, m3);
    m0 = fmaxf(m0 + xv.x, 0.f);
    m1 = fmaxf(m1 + xv.y, 0.f);
    m2 = fmaxf(m2 + xv.z, 0.f);
    m3 = fmaxf(m3 + xv.w, 0.f);

    float* p = aggr + (size_t)dst * DIM + l * 4;
    asm volatile("red.global.add.v4.f32 [%0], {%1,%2,%3,%4};"
                 :: "l"(p), "f"(m0), "f"(m1), "f"(m2), "f"(m3)
                 : "memory");
}

// ---------------------------------------------------------------------------
// Kernel 3: node epilogue. 8 nodes/warp, packed f32x2 MLP + LN + ReLU.
// ---------------------------------------------------------------------------
#define NPW 8
__global__ __launch_bounds__(256, 4) void node_kernel(
    const float2* __restrict__ x,
    const float* __restrict__ W1,
    const float* __restrict__ b1,
    const float* __restrict__ W2,
    const float* __restrict__ b2,
    const float* __restrict__ gamma,
    const float* __restrict__ beta,
    float2* __restrict__ out)     // holds aggr on entry; overwritten in place
{
    __shared__ unsigned long long W1p[32 * 64];   // 16 KB
    __shared__ unsigned long long W2p[32 * 64];   // 16 KB
    __shared__ float hs[8][NPW * DIM];            // 16 KB

    int tid = threadIdx.x;
    for (int i = tid; i < 32 * 64; i += 256) {
        int k2 = i >> 6, c = i & 63;
        W1p[i] = f2_as_u64(W1[(2 * k2) * 64 + c], W1[(2 * k2 + 1) * 64 + c]);
        W2p[i] = f2_as_u64(W2[(2 * k2) * 64 + c], W2[(2 * k2 + 1) * 64 + c]);
    }
    __syncthreads();

    int w = tid >> 5, lane = tid & 31;
    int base = (blockIdx.x * 8 + w) * NPW;
    if (base >= N_NODES) return;
    float* h = hs[w];

#pragma unroll
    for (int n = 0; n < NPW; n++) {
        int node = base + n;
        if (node < N_NODES) {
            float2 xv = x[(size_t)node * 32 + lane];
            float2 av = out[(size_t)node * 32 + lane];
            *(float2*)&h[n * DIM + 2 * lane] = make_float2(xv.x + av.x, xv.y + av.y);
        }
    }
    __syncwarp();

    unsigned long long accA[NPW], accB[NPW];

    // ---- layer 1 ----
    {
        float bA = b1[2 * lane], bB = b1[2 * lane + 1];
#pragma unroll
        for (int n = 0; n < NPW; n++) {
            accA[n] = f2_as_u64(bA, 0.f);
            accB[n] = f2_as_u64(bB, 0.f);
        }
    }
#pragma unroll
    for (int k2 = 0; k2 < 32; k2++) {
        ulonglong2 wp = *(const ulonglong2*)&W1p[k2 * 64 + 2 * lane];
#pragma unroll
        for (int n = 0; n < NPW; n++) {
            unsigned long long h2 = *(const unsigned long long*)&h[n * DIM + 2 * k2];
            ffma2(accA[n], h2, wp.x);
            ffma2(accB[n], h2, wp.y);
        }
    }
    __syncwarp();
#pragma unroll
    for (int n = 0; n < NPW; n++) {
        float ax, ay, bx, by;
        u64_as_f2(accA[n], ax, ay);
        u64_as_f2(accB[n], bx, by);
        *(float2*)&h[n * DIM + 2 * lane] =
            make_float2(fmaxf(ax + ay, 0.f), fmaxf(bx + by, 0.f));
    }
    __syncwarp();

    // ---- layer 2 ----
    {
        float bA = b2[2 * lane], bB = b2[2 * lane + 1];
#pragma unroll
        for (int n = 0; n < NPW; n++) {
            accA[n] = f2_as_u64(bA, 0.f);
            accB[n] = f2_as_u64(bB, 0.f);
        }
    }
#pragma unroll
    for (int k2 = 0; k2 < 32; k2++) {
        ulonglong2 wp = *(const ulonglong2*)&W2p[k2 * 64 + 2 * lane];
#pragma unroll
        for (int n = 0; n < NPW; n++) {
            unsigned long long h2 = *(const unsigned long long*)&h[n * DIM + 2 * k2];
            ffma2(accA[n], h2, wp.x);
            ffma2(accB[n], h2, wp.y);
        }
    }

    // ---- LayerNorm + ReLU ----
    float2 g  = make_float2(gamma[2 * lane], gamma[2 * lane + 1]);
    float2 bt = make_float2(beta[2 * lane],  beta[2 * lane + 1]);
    const float inv = 1.0f / DIM;

#pragma unroll
    for (int n = 0; n < NPW; n++) {
        float ax, ay, bx, by;
        u64_as_f2(accA[n], ax, ay);
        u64_as_f2(accB[n], bx, by);
        float v0 = ax + ay, v1 = bx + by;
        float s = v0 + v1, q = v0 * v0 + v1 * v1;
#pragma unroll
        for (int o = 16; o > 0; o >>= 1) {
            s += __shfl_xor_sync(0xffffffffu, s, o);
            q += __shfl_xor_sync(0xffffffffu, q, o);
        }
        float mu  = s * inv;
        float var = fmaxf(q * inv - mu * mu, 0.f);
        float r   = rsqrtf(var + 1e-5f);
        int node = base + n;
        if (node < N_NODES) {
            float2 o2;
            o2.x = fmaxf((v0 - mu) * r * g.x + bt.x, 0.f);
            o2.y = fmaxf((v1 - mu) * r * g.y + bt.y, 0.f);
            out[(size_t)node * 32 + lane] = o2;
        }
    }
}

// ---------------------------------------------------------------------------
// Launch
// ---------------------------------------------------------------------------
extern "C" void kernel_launch(void* const* d_in, const int* in_sizes, int n_in,
                              void* d_out, int out_size) {
    const float* x     = (const float*)d_in[0];
    const void*  ei    = d_in[1];
    const float* ea    = (const float*)d_in[2];
    const float* We    = (const float*)d_in[3];
    const float* be    = (const float*)d_in[4];
    const float* W1    = (const float*)d_in[5];
    const float* b1    = (const float*)d_in[6];
    const float* W2    = (const float*)d_in[7];
    const float* b2    = (const float*)d_in[8];
    const float* gamma = (const float*)d_in[9];
    const float* beta  = (const float*)d_in[10];
    float* out = (float*)d_out;

    // 1) zero accumulator + detect index dtype
    int n4 = N_NODES * DIM / 4;
    zero_detect_kernel<<<(n4 + 255) / 256, 256>>>((float4*)out, n4,
                                                  (const unsigned int*)ei);

    // 2) edge messages + atomic scatter: 16 edges/block, exact grid
    edge_kernel<<<N_EDGES / 16, 256>>>((const float4*)x, ei, (const float4*)ea,
                                       (const float4*)be, (const float4*)We, out);

    // 3) node MLP + LayerNorm: 64 nodes/block
    node_kernel<<<(N_NODES + 63) / 64, 256>>>((const float2*)x, W1, b1, W2, b2,
                                              gamma, beta, (float2*)out);
}